// round 14
// baseline (speedup 1.0000x reference)
#include <cuda_runtime.h>
#include <cuda_bf16.h>
#include <cstdint>
#include <cstddef>

// Problem constants
#define Hh      8
#define SS      2048
#define DM      512
#define DH      64
#define BATCH   4
#define BHN     (BATCH * Hh)          // 32
#define MQ      (BATCH * SS)          // 8192
#define OUT_ELEMS ((size_t)BATCH * SS * DM)  // 4194304
#define NSLC    64                    // stats slices per row (32-col slices)

// Scratch (allocation-free: __device__ globals).
__device__ __nv_bfloat16 g_Qh [BHN * SS * DH];
__device__ __nv_bfloat16 g_Ql [BHN * SS * DH];
__device__ __nv_bfloat16 g_Kh [BHN * SS * DH];
__device__ __nv_bfloat16 g_Kl [BHN * SS * DH];
__device__ __nv_bfloat16 g_Vth[BHN * DH * SS];   // V^T hi: [bh][d][s]
__device__ __nv_bfloat16 g_Vtl[BHN * DH * SS];   // V^T lo
__device__ __nv_bfloat16 g_Hh [BHN * SS * DH];   // attn-out hi: [bh][s][d]
__device__ __nv_bfloat16 g_Hl [BHN * SS * DH];   // attn-out lo
__device__ float2 g_stats [(size_t)BHN * SS * NSLC]; // per-(row, 32col-slice) {M, S}
__device__ float2 g_rowMS [(size_t)BHN * SS];        // per-row {M, 1/S}

// ===========================================================================
// Warp-level MMA helpers (sm_80-compatible PTX)
// ===========================================================================
__device__ __forceinline__ uint32_t smem_u32(const void* p) {
    uint32_t a;
    asm("{ .reg .u64 t; cvta.to.shared.u64 t, %1; cvt.u32.u64 %0, t; }"
        : "=r"(a) : "l"(p));
    return a;
}
__device__ __forceinline__ void mma16816(float* c, const uint32_t* a, const uint32_t* b) {
    asm volatile(
        "mma.sync.aligned.m16n8k16.row.col.f32.bf16.bf16.f32 "
        "{%0,%1,%2,%3}, {%4,%5,%6,%7}, {%8,%9}, {%0,%1,%2,%3};"
        : "+f"(c[0]), "+f"(c[1]), "+f"(c[2]), "+f"(c[3])
        : "r"(a[0]), "r"(a[1]), "r"(a[2]), "r"(a[3]), "r"(b[0]), "r"(b[1]));
}
__device__ __forceinline__ void ldm_x4(uint32_t* r, uint32_t addr) {
    asm volatile("ldmatrix.sync.aligned.m8n8.x4.shared.b16 {%0,%1,%2,%3}, [%4];"
        : "=r"(r[0]), "=r"(r[1]), "=r"(r[2]), "=r"(r[3]) : "r"(addr));
}
__device__ __forceinline__ void ldm_x2(uint32_t* r, uint32_t addr) {
    asm volatile("ldmatrix.sync.aligned.m8n8.x2.shared.b16 {%0,%1}, [%2];"
        : "=r"(r[0]), "=r"(r[1]) : "r"(addr));
}
__device__ __forceinline__ void split_bf16(float v, __nv_bfloat16& h, __nv_bfloat16& l) {
    h = __float2bfloat16(v);
    l = __float2bfloat16(v - __bfloat162float(h));
}

#define SPAD  72    // row pitch in bf16 elems (144B), conflict-free ldmatrix
#define FPITCH 132  // (unused legacy)

// smem tile offsets (bf16 elems) for 4-operand kernels (proj/stats/oproj)
#define T_AH 0
#define T_AL (128 * SPAD)
#define T_BH (2 * 128 * SPAD)
#define T_BL (3 * 128 * SPAD)
#define OPER_SMEM (4 * 128 * SPAD * 2)    // 73728 B

// av_fused smem offsets (bf16 elems)
#define F_QH 0
#define F_QL (128 * SPAD)
#define F_KH (256 * SPAD)
#define F_KL (320 * SPAD)
#define F_VH (384 * SPAD)
#define F_VL (448 * SPAD)
#define F_PH (512 * SPAD)
#define F_PL (640 * SPAD)
#define AVF_SMEM (768 * SPAD * 2)         // 110592 B

// ---------------------------------------------------------------------------
// Shared compensated mainloop (proj/stats/oproj): per ks: H*H, H*L, L*H
// ---------------------------------------------------------------------------
#define COMP_MAINLOOP_4x4(sbase, arow, acol8, brow, bcol8, acc)              \
    _Pragma("unroll")                                                        \
    for (int ks = 0; ks < 4; ks++) {                                         \
        const int k0 = ks * 16;                                              \
        uint32_t aH[4][4], aL[4][4], bH[4][2], bL[4][2];                     \
        _Pragma("unroll")                                                    \
        for (int mt = 0; mt < 4; mt++)                                       \
            ldm_x4(aH[mt], (sbase) + 2u * (T_AH + ((arow) + mt*16) * SPAD + k0 + (acol8))); \
        _Pragma("unroll")                                                    \
        for (int nt = 0; nt < 4; nt++)                                       \
            ldm_x2(bH[nt], (sbase) + 2u * (T_BH + ((brow) + nt*8) * SPAD + k0 + (bcol8))); \
        _Pragma("unroll")                                                    \
        for (int mt = 0; mt < 4; mt++)                                       \
            _Pragma("unroll")                                                \
            for (int nt = 0; nt < 4; nt++)                                   \
                mma16816(acc[mt][nt], aH[mt], bH[nt]);                       \
        _Pragma("unroll")                                                    \
        for (int nt = 0; nt < 4; nt++)                                       \
            ldm_x2(bL[nt], (sbase) + 2u * (T_BL + ((brow) + nt*8) * SPAD + k0 + (bcol8))); \
        _Pragma("unroll")                                                    \
        for (int mt = 0; mt < 4; mt++)                                       \
            _Pragma("unroll")                                                \
            for (int nt = 0; nt < 4; nt++)                                   \
                mma16816(acc[mt][nt], aH[mt], bL[nt]);                       \
        _Pragma("unroll")                                                    \
        for (int mt = 0; mt < 4; mt++)                                       \
            ldm_x4(aL[mt], (sbase) + 2u * (T_AL + ((arow) + mt*16) * SPAD + k0 + (acol8))); \
        _Pragma("unroll")                                                    \
        for (int mt = 0; mt < 4; mt++)                                       \
            _Pragma("unroll")                                                \
            for (int nt = 0; nt < 4; nt++)                                   \
                mma16816(acc[mt][nt], aL[mt], bH[nt]);                       \
    }

// ---------------------------------------------------------------------------
// Kernel 1: merged QKV projection via mma.sync (unchanged from R12).
// grid (4, 64, 3), block 256
// ---------------------------------------------------------------------------
__global__ __launch_bounds__(256, 2)
void proj_mma_kernel(const float* __restrict__ Xq, const float* __restrict__ Xk,
                     const float* __restrict__ Xv,
                     const float* __restrict__ Wq, const float* __restrict__ Wk,
                     const float* __restrict__ Wv,
                     const float* __restrict__ bq, const float* __restrict__ bk,
                     const float* __restrict__ bv)
{
    extern __shared__ __nv_bfloat16 sm[];
    const int which = blockIdx.z;
    const float* X    = (which == 0) ? Xq : (which == 1) ? Xk : Xv;
    const float* W    = (which == 0) ? Wq : (which == 1) ? Wk : Wv;
    const float* bias = (which == 0) ? bq : (which == 1) ? bk : bv;

    const int t    = threadIdx.x;
    const int wid  = t >> 5;
    const int lane = t & 31;
    const int m0   = blockIdx.y * 128;
    const int n0   = blockIdx.x * 128;

    const uint32_t sbase = smem_u32(sm);
    const int warp_m = wid >> 2;
    const int warp_n = wid & 3;

    float acc[4][4][4];
#pragma unroll
    for (int mt = 0; mt < 4; mt++)
#pragma unroll
        for (int nt = 0; nt < 4; nt++)
#pragma unroll
            for (int e = 0; e < 4; e++) acc[mt][nt][e] = 0.f;

    const int l16   = lane & 15;
    const int arow  = warp_m * 64 + (lane & 15);
    const int acol8 = (lane >> 4) * 8;
    const int brow  = warp_n * 32 + (l16 & 7);
    const int bcol8 = (l16 >> 3) * 8;

    const int lr_base = t >> 4;     // 0..15
    const int lcol    = (t & 15) * 4;

    for (int kb = 0; kb < DM; kb += 64) {
#pragma unroll
        for (int p = 0; p < 8; p++) {
            const int row = lr_base + p * 16;
            float4 xv = *(const float4*)(X + (size_t)(m0 + row) * DM + kb + lcol);
            float4 wv = *(const float4*)(W + (size_t)(n0 + row) * DM + kb + lcol);
            __nv_bfloat16 h0,h1,h2,h3,l0,l1,l2,l3;
            split_bf16(xv.x,h0,l0); split_bf16(xv.y,h1,l1);
            split_bf16(xv.z,h2,l2); split_bf16(xv.w,h3,l3);
            __nv_bfloat162* pa = (__nv_bfloat162*)(sm + T_AH + row * SPAD + lcol);
            pa[0] = __nv_bfloat162(h0,h1); pa[1] = __nv_bfloat162(h2,h3);
            __nv_bfloat162* qa = (__nv_bfloat162*)(sm + T_AL + row * SPAD + lcol);
            qa[0] = __nv_bfloat162(l0,l1); qa[1] = __nv_bfloat162(l2,l3);
            split_bf16(wv.x,h0,l0); split_bf16(wv.y,h1,l1);
            split_bf16(wv.z,h2,l2); split_bf16(wv.w,h3,l3);
            __nv_bfloat162* pb = (__nv_bfloat162*)(sm + T_BH + row * SPAD + lcol);
            pb[0] = __nv_bfloat162(h0,h1); pb[1] = __nv_bfloat162(h2,h3);
            __nv_bfloat162* qb = (__nv_bfloat162*)(sm + T_BL + row * SPAD + lcol);
            qb[0] = __nv_bfloat162(l0,l1); qb[1] = __nv_bfloat162(l2,l3);
        }
        __syncthreads();

        COMP_MAINLOOP_4x4(sbase, arow, acol8, brow, bcol8, acc)

        __syncthreads();
    }

    const int b_  = m0 >> 11;
    const int lr0 = warp_m * 64 + (lane >> 2);
    const int cb0 = warp_n * 32 + (lane & 3) * 2;
#pragma unroll
    for (int mt = 0; mt < 4; mt++) {
#pragma unroll
        for (int rr = 0; rr < 2; rr++) {
            const int s_ = (m0 & 2047) + lr0 + mt * 16 + rr * 8;
#pragma unroll
            for (int nt = 0; nt < 4; nt++) {
                const int n  = n0 + cb0 + nt * 8;
                const int h  = n >> 6, d = n & 63;
                const int bh = b_ * Hh + h;
                const float v0 = acc[mt][nt][rr*2+0] + bias[n];
                const float v1 = acc[mt][nt][rr*2+1] + bias[n+1];
                __nv_bfloat16 h0,h1,l0,l1;
                split_bf16(v0,h0,l0); split_bf16(v1,h1,l1);
                if (which == 2) {
                    const size_t i0 = ((size_t)bh * DH + d) * SS + s_;
                    const size_t i1 = ((size_t)bh * DH + d + 1) * SS + s_;
                    g_Vth[i0] = h0; g_Vtl[i0] = l0;
                    g_Vth[i1] = h1; g_Vtl[i1] = l1;
                } else {
                    const size_t idx = ((size_t)bh * SS + s_) * DH + d;
                    if (which == 0) {
                        *(__nv_bfloat162*)(g_Qh + idx) = __nv_bfloat162(h0,h1);
                        *(__nv_bfloat162*)(g_Ql + idx) = __nv_bfloat162(l0,l1);
                    } else {
                        *(__nv_bfloat162*)(g_Kh + idx) = __nv_bfloat162(h0,h1);
                        *(__nv_bfloat162*)(g_Kl + idx) = __nv_bfloat162(l0,l1);
                    }
                }
            }
        }
    }
}

// ---------------------------------------------------------------------------
// Kernel 2: stats only — S = QK^T*0.125 + mask; per-(row, 32col-slice) {M,S}.
// NO att write. In-register quad reduction.
// grid (16, 16, 32), block 256
// ---------------------------------------------------------------------------
__global__ __launch_bounds__(256, 2)
void stats_mma_kernel(const float* __restrict__ mask)
{
    extern __shared__ __nv_bfloat16 sm[];
    const int t    = threadIdx.x;
    const int wid  = t >> 5;
    const int lane = t & 31;

    const int bh = blockIdx.z;
    const int m0 = blockIdx.y * 128;
    const int n0 = blockIdx.x * 128;

    {
        const size_t rb = (size_t)bh * SS * DH;
        const int qi = t & 7;
#pragma unroll
        for (int p = 0; p < 4; p++) {
            const int row = (t >> 3) + p * 32;
            const size_t qoff = rb + (size_t)(m0 + row) * DH + qi * 8;
            const size_t koff = rb + (size_t)(n0 + row) * DH + qi * 8;
            *(uint4*)(sm + T_AH + row * SPAD + qi * 8) = *(const uint4*)(g_Qh + qoff);
            *(uint4*)(sm + T_AL + row * SPAD + qi * 8) = *(const uint4*)(g_Ql + qoff);
            *(uint4*)(sm + T_BH + row * SPAD + qi * 8) = *(const uint4*)(g_Kh + koff);
            *(uint4*)(sm + T_BL + row * SPAD + qi * 8) = *(const uint4*)(g_Kl + koff);
        }
    }
    __syncthreads();

    const uint32_t sbase = smem_u32(sm);
    const int warp_m = wid >> 2;
    const int warp_n = wid & 3;

    float acc[4][4][4];
#pragma unroll
    for (int mt = 0; mt < 4; mt++)
#pragma unroll
        for (int nt = 0; nt < 4; nt++)
#pragma unroll
            for (int e = 0; e < 4; e++) acc[mt][nt][e] = 0.f;

    const int l16   = lane & 15;
    const int arow  = warp_m * 64 + (lane & 15);
    const int acol8 = (lane >> 4) * 8;
    const int brow  = warp_n * 32 + (l16 & 7);
    const int bcol8 = (l16 >> 3) * 8;

    COMP_MAINLOOP_4x4(sbase, arow, acol8, brow, bcol8, acc)

    // In-register stats: each quad (lanes q*4..q*4+3) owns full rows.
    const int lr0 = warp_m * 64 + (lane >> 2);
    const int cb0 = warp_n * 32 + (lane & 3) * 2;
#pragma unroll
    for (int mt = 0; mt < 4; mt++) {
#pragma unroll
        for (int rr = 0; rr < 2; rr++) {
            const int grow = m0 + lr0 + mt * 16 + rr * 8;
            const float* mrow = mask + (size_t)grow * SS + n0;
            float v[8];
#pragma unroll
            for (int nt = 0; nt < 4; nt++) {
                float2 mv = *(const float2*)(mrow + cb0 + nt * 8);
                v[nt*2+0] = acc[mt][nt][rr*2+0] * 0.125f + mv.x;
                v[nt*2+1] = acc[mt][nt][rr*2+1] * 0.125f + mv.y;
            }
            float mx = v[0];
#pragma unroll
            for (int i = 1; i < 8; i++) mx = fmaxf(mx, v[i]);
            mx = fmaxf(mx, __shfl_xor_sync(0xFFFFFFFFu, mx, 1));
            mx = fmaxf(mx, __shfl_xor_sync(0xFFFFFFFFu, mx, 2));
            float s = 0.f;
#pragma unroll
            for (int i = 0; i < 8; i++) s += __expf(v[i] - mx);
            s += __shfl_xor_sync(0xFFFFFFFFu, s, 1);
            s += __shfl_xor_sync(0xFFFFFFFFu, s, 2);
            if ((lane & 3) == 0)
                g_stats[((size_t)bh * SS + grow) * NSLC + blockIdx.x * 4 + warp_n] =
                    make_float2(mx, s);
        }
    }
}

// ---------------------------------------------------------------------------
// Kernel 3: reduce 64 partials per row -> {M, 1/S}. One warp per row.
// grid 8192, block 256 (8 warps)
// ---------------------------------------------------------------------------
__global__ __launch_bounds__(256)
void reduce_stats_kernel()
{
    const int wid  = threadIdx.x >> 5;
    const int lane = threadIdx.x & 31;
    const size_t r = (size_t)blockIdx.x * 8 + wid;
    const float2* p = g_stats + r * NSLC;
    float2 a = p[lane];
    float2 b = p[lane + 32];
    float M = fmaxf(a.x, b.x);
    float S = a.y * __expf(a.x - M) + b.y * __expf(b.x - M);
#pragma unroll
    for (int off = 16; off > 0; off >>= 1) {
        float Mo = __shfl_xor_sync(0xFFFFFFFFu, M, off);
        float So = __shfl_xor_sync(0xFFFFFFFFu, S, off);
        float Mn = fmaxf(M, Mo);
        S = S * __expf(M - Mn) + So * __expf(Mo - Mn);
        M = Mn;
    }
    if (lane == 0) g_rowMS[r] = make_float2(M, 1.0f / S);
}

// ---------------------------------------------------------------------------
// Kernel 4: av_fused — recompute scores, normalize, write att, PV MMA.
// grid (32, 16): x = bh, y = m-tile(128). block 256 (8 warps 2x4).
// Per n-block of 64: K/V load -> scores MMA (P acc) -> transform (mask, exp,
// split to P smem) -> att write (h+l, coalesced) + PV MMA into O acc.
// ---------------------------------------------------------------------------
__global__ __launch_bounds__(256, 2)
void av_fused_kernel(const float* __restrict__ mask, float* __restrict__ att)
{
    extern __shared__ __nv_bfloat16 sm[];
    const int t    = threadIdx.x;
    const int wid  = t >> 5;
    const int lane = t & 31;

    const int bh = blockIdx.x;
    const int m0 = blockIdx.y * 128;

    const uint32_t sbase = smem_u32(sm);
    const int warp_m = wid >> 2;          // 0..1 (m64)
    const int warp_n = wid & 3;           // 0..3 (n16 / d16)

    const int l16   = lane & 15;
    const int arow  = warp_m * 64 + l16;
    const int acol8 = (lane >> 4) * 8;
    const int brow  = warp_n * 16 + (l16 & 7);
    const int bcol8 = (l16 >> 3) * 8;

    // Load Q tile (128 x 64 hi/lo) once.
    {
        const size_t rb = (size_t)bh * SS * DH;
        const int qi = t & 7;
#pragma unroll
        for (int p = 0; p < 4; p++) {
            const int row = (t >> 3) + p * 32;
            const size_t qoff = rb + (size_t)(m0 + row) * DH + qi * 8;
            *(uint4*)(sm + F_QH + row * SPAD + qi * 8) = *(const uint4*)(g_Qh + qoff);
            *(uint4*)(sm + F_QL + row * SPAD + qi * 8) = *(const uint4*)(g_Ql + qoff);
        }
    }

    // Per-thread row stats for the 8 P-fragment rows.
    const int prow0 = warp_m * 64 + (lane >> 2);
    const int pcol0 = warp_n * 16 + (lane & 3) * 2;
    float2 ms[8];
#pragma unroll
    for (int mt = 0; mt < 4; mt++)
#pragma unroll
        for (int rr = 0; rr < 2; rr++)
            ms[mt*2+rr] = g_rowMS[(size_t)bh * SS + m0 + prow0 + mt*16 + rr*8];

    // O accumulators (m64 x d16 per warp)
    float oacc[4][2][4];
#pragma unroll
    for (int mt = 0; mt < 4; mt++)
#pragma unroll
        for (int nt = 0; nt < 2; nt++)
#pragma unroll
            for (int e = 0; e < 4; e++) oacc[mt][nt][e] = 0.f;

    const int lqi  = t & 7;          // K/V loader: 8 thr/row
    const int lrb  = t >> 4;         // att writer: 16 thr/row
    const int c0   = (t & 15) * 4;

    for (int nb = 0; nb < SS / 64; nb++) {
        const int n0 = nb * 64;
        __syncthreads();   // protect K/V/P smem from previous iteration readers

        // Load K tile (rows n0..n0+63, 64 d) and V^T chunk (64 d rows, cols n0..n0+63)
        {
            const size_t rbk = (size_t)bh * SS * DH;
#pragma unroll
            for (int p = 0; p < 2; p++) {
                const int row = (t >> 3) + p * 32;
                const size_t koff = rbk + (size_t)(n0 + row) * DH + lqi * 8;
                *(uint4*)(sm + F_KH + row * SPAD + lqi * 8) = *(const uint4*)(g_Kh + koff);
                *(uint4*)(sm + F_KL + row * SPAD + lqi * 8) = *(const uint4*)(g_Kl + koff);
                const size_t voff = ((size_t)bh * DH + row) * SS + n0 + lqi * 8;
                *(uint4*)(sm + F_VH + row * SPAD + lqi * 8) = *(const uint4*)(g_Vth + voff);
                *(uint4*)(sm + F_VL + row * SPAD + lqi * 8) = *(const uint4*)(g_Vtl + voff);
            }
        }
        __syncthreads();

        // Scores MMA: P = Q K^T (m64 x n16 per warp), compensated.
        float pacc[4][2][4];
#pragma unroll
        for (int mt = 0; mt < 4; mt++)
#pragma unroll
            for (int nt = 0; nt < 2; nt++)
#pragma unroll
                for (int e = 0; e < 4; e++) pacc[mt][nt][e] = 0.f;

#pragma unroll
        for (int ks = 0; ks < 4; ks++) {
            const int k0 = ks * 16;
            uint32_t aH[4][4], aL[4][4], bH[2][2], bL[2][2];
#pragma unroll
            for (int mt = 0; mt < 4; mt++)
                ldm_x4(aH[mt], sbase + 2u * (F_QH + (arow + mt*16) * SPAD + k0 + acol8));
#pragma unroll
            for (int nt = 0; nt < 2; nt++)
                ldm_x2(bH[nt], sbase + 2u * (F_KH + (brow + nt*8) * SPAD + k0 + bcol8));
#pragma unroll
            for (int mt = 0; mt < 4; mt++)
#pragma unroll
                for (int nt = 0; nt < 2; nt++)
                    mma16816(pacc[mt][nt], aH[mt], bH[nt]);
#pragma unroll
            for (int nt = 0; nt < 2; nt++)
                ldm_x2(bL[nt], sbase + 2u * (F_KL + (brow + nt*8) * SPAD + k0 + bcol8));
#pragma unroll
            for (int mt = 0; mt < 4; mt++)
#pragma unroll
                for (int nt = 0; nt < 2; nt++)
                    mma16816(pacc[mt][nt], aH[mt], bL[nt]);
#pragma unroll
            for (int mt = 0; mt < 4; mt++)
                ldm_x4(aL[mt], sbase + 2u * (F_QL + (arow + mt*16) * SPAD + k0 + acol8));
#pragma unroll
            for (int mt = 0; mt < 4; mt++)
#pragma unroll
                for (int nt = 0; nt < 2; nt++)
                    mma16816(pacc[mt][nt], aL[mt], bH[nt]);
        }

        // Transform: mask + scale + exp-normalize -> P smem (hi/lo).
#pragma unroll
        for (int mt = 0; mt < 4; mt++) {
#pragma unroll
            for (int rr = 0; rr < 2; rr++) {
                const int rl = prow0 + mt * 16 + rr * 8;
                const float2 msv = ms[mt*2+rr];
                const float* mrow = mask + (size_t)(m0 + rl) * SS + n0;
#pragma unroll
                for (int nt = 0; nt < 2; nt++) {
                    const int c = pcol0 + nt * 8;
                    float2 mv = *(const float2*)(mrow + c);
                    const float s0 = pacc[mt][nt][rr*2+0] * 0.125f + mv.x;
                    const float s1 = pacc[mt][nt][rr*2+1] * 0.125f + mv.y;
                    const float p0 = __expf(s0 - msv.x) * msv.y;
                    const float p1 = __expf(s1 - msv.x) * msv.y;
                    __nv_bfloat16 h0,h1,l0,l1;
                    split_bf16(p0,h0,l0); split_bf16(p1,h1,l1);
                    *(__nv_bfloat162*)(sm + F_PH + rl * SPAD + c) = __nv_bfloat162(h0,h1);
                    *(__nv_bfloat162*)(sm + F_PL + rl * SPAD + c) = __nv_bfloat162(l0,l1);
                }
            }
        }
        __syncthreads();

        // att write (coalesced, from P smem: h + l)
#pragma unroll
        for (int p = 0; p < 8; p++) {
            const int row = lrb + p * 16;
            const __nv_bfloat162* ph = (const __nv_bfloat162*)(sm + F_PH + row * SPAD + c0);
            const __nv_bfloat162* pl = (const __nv_bfloat162*)(sm + F_PL + row * SPAD + c0);
            __nv_bfloat162 h01 = ph[0], h23 = ph[1];
            __nv_bfloat162 l01 = pl[0], l23 = pl[1];
            float4 v;
            v.x = __bfloat162float(h01.x) + __bfloat162float(l01.x);
            v.y = __bfloat162float(h01.y) + __bfloat162float(l01.y);
            v.z = __bfloat162float(h23.x) + __bfloat162float(l23.x);
            v.w = __bfloat162float(h23.y) + __bfloat162float(l23.y);
            __stcs((float4*)(att + ((size_t)bh * SS + m0 + row) * SS + n0 + c0), v);
        }

        // PV MMA: O += P V^T (m64 x d16 per warp), compensated.
#pragma unroll
        for (int ks = 0; ks < 4; ks++) {
            const int k0 = ks * 16;
            uint32_t aH[4][4], aL[4][4], bH[2][2], bL[2][2];
#pragma unroll
            for (int mt = 0; mt < 4; mt++) {
                ldm_x4(aH[mt], sbase + 2u * (F_PH + (arow + mt*16) * SPAD + k0 + acol8));
                ldm_x4(aL[mt], sbase + 2u * (F_PL + (arow + mt*16) * SPAD + k0 + acol8));
            }
#pragma unroll
            for (int nt = 0; nt < 2; nt++) {
                ldm_x2(bH[nt], sbase + 2u * (F_VH + (brow + nt*8) * SPAD + k0 + bcol8));
                ldm_x2(bL[nt], sbase + 2u * (F_VL + (brow + nt*8) * SPAD + k0 + bcol8));
            }
#pragma unroll
            for (int mt = 0; mt < 4; mt++)
#pragma unroll
                for (int nt = 0; nt < 2; nt++) {
                    mma16816(oacc[mt][nt], aH[mt], bH[nt]);
                    mma16816(oacc[mt][nt], aH[mt], bL[nt]);
                    mma16816(oacc[mt][nt], aL[mt], bH[nt]);
                }
        }
    }

    // Epilogue -> g_Hh/g_Hl bf16 hi/lo, [bh][s][d]
    const int orow = m0 + prow0;
    const int ocb0 = warp_n * 16 + (lane & 3) * 2;
#pragma unroll
    for (int mt = 0; mt < 4; mt++) {
#pragma unroll
        for (int rr = 0; rr < 2; rr++) {
            const int r = orow + mt * 16 + rr * 8;
#pragma unroll
            for (int nt = 0; nt < 2; nt++) {
                const int cb = ocb0 + nt * 8;
                const float v0 = oacc[mt][nt][rr*2+0];
                const float v1 = oacc[mt][nt][rr*2+1];
                __nv_bfloat16 h0,h1,l0,l1;
                split_bf16(v0,h0,l0); split_bf16(v1,h1,l1);
                const size_t idx = ((size_t)bh * SS + r) * DH + cb;
                *(__nv_bfloat162*)(g_Hh + idx) = __nv_bfloat162(h0,h1);
                *(__nv_bfloat162*)(g_Hl + idx) = __nv_bfloat162(l0,l1);
            }
        }
    }
}

// ---------------------------------------------------------------------------
// Kernel 5: output projection via mma.sync (unchanged from R12).
// grid (4, 64), block 256
// ---------------------------------------------------------------------------
__global__ __launch_bounds__(256, 2)
void oproj_mma_kernel(const float* __restrict__ Wo, const float* __restrict__ bo,
                      float* __restrict__ out)
{
    extern __shared__ __nv_bfloat16 sm[];
    const int t    = threadIdx.x;
    const int wid  = t >> 5;
    const int lane = t & 31;
    const int m0   = blockIdx.y * 128;
    const int n0   = blockIdx.x * 128;
    const int b_   = m0 >> 11;
    const int s0   = m0 & 2047;

    const uint32_t sbase = smem_u32(sm);
    const int warp_m = wid >> 2;
    const int warp_n = wid & 3;

    float acc[4][4][4];
#pragma unroll
    for (int mt = 0; mt < 4; mt++)
#pragma unroll
        for (int nt = 0; nt < 4; nt++)
#pragma unroll
            for (int e = 0; e < 4; e++) acc[mt][nt][e] = 0.f;

    const int l16   = lane & 15;
    const int arow  = warp_m * 64 + (lane & 15);
    const int acol8 = (lane >> 4) * 8;
    const int brow  = warp_n * 32 + (l16 & 7);
    const int bcol8 = (l16 >> 3) * 8;

    const int aqi = t & 7;
    const int wlr = t >> 4;
    const int wc0 = (t & 15) * 4;

    for (int kb = 0; kb < 8; kb++) {
#pragma unroll
        for (int p = 0; p < 4; p++) {
            const int row = (t >> 3) + p * 32;
            const size_t hoff = (((size_t)(b_ * Hh + kb) * SS) + s0 + row) * DH + aqi * 8;
            *(uint4*)(sm + T_AH + row * SPAD + aqi * 8) = *(const uint4*)(g_Hh + hoff);
            *(uint4*)(sm + T_AL + row * SPAD + aqi * 8) = *(const uint4*)(g_Hl + hoff);
        }
#pragma unroll
        for (int p = 0; p < 8; p++) {
            const int row = wlr + p * 16;
            float4 wv = *(const float4*)(Wo + (size_t)(n0 + row) * DM + kb * 64 + wc0);
            __nv_bfloat16 h0,h1,h2,h3,l0,l1,l2,l3;
            split_bf16(wv.x,h0,l0); split_bf16(wv.y,h1,l1);
            split_bf16(wv.z,h2,l2); split_bf16(wv.w,h3,l3);
            __nv_bfloat162* pb = (__nv_bfloat162*)(sm + T_BH + row * SPAD + wc0);
            pb[0] = __nv_bfloat162(h0,h1); pb[1] = __nv_bfloat162(h2,h3);
            __nv_bfloat162* qb = (__nv_bfloat162*)(sm + T_BL + row * SPAD + wc0);
            qb[0] = __nv_bfloat162(l0,l1); qb[1] = __nv_bfloat162(l2,l3);
        }
        __syncthreads();

        COMP_MAINLOOP_4x4(sbase, arow, acol8, brow, bcol8, acc)

        __syncthreads();
    }

    const int lr0 = warp_m * 64 + (lane >> 2);
    const int cb0 = warp_n * 32 + (lane & 3) * 2;
#pragma unroll
    for (int mt = 0; mt < 4; mt++) {
#pragma unroll
        for (int rr = 0; rr < 2; rr++) {
            const int mm = m0 + lr0 + mt * 16 + rr * 8;
#pragma unroll
            for (int nt = 0; nt < 4; nt++) {
                const int n = n0 + cb0 + nt * 8;
                *(float2*)(out + (size_t)mm * DM + n) =
                    make_float2(acc[mt][nt][rr*2+0] + bo[n],
                                acc[mt][nt][rr*2+1] + bo[n+1]);
            }
        }
    }
}

// ---------------------------------------------------------------------------
extern "C" void kernel_launch(void* const* d_in, const int* in_sizes, int n_in,
                              void* d_out, int out_size)
{
    const float* queries = (const float*)d_in[0];
    const float* keys    = (const float*)d_in[1];
    const float* values  = (const float*)d_in[2];
    const float* mask    = (const float*)d_in[3];
    const float* Wq      = (const float*)d_in[4];
    const float* bq      = (const float*)d_in[5];
    const float* Wk      = (const float*)d_in[6];
    const float* bk      = (const float*)d_in[7];
    const float* Wv      = (const float*)d_in[8];
    const float* bv      = (const float*)d_in[9];
    const float* Wo      = (const float*)d_in[10];
    const float* bo      = (const float*)d_in[11];

    float* out = (float*)d_out;            // [4, 2048, 512]
    float* att = out + OUT_ELEMS;          // [4, 8, 2048, 2048]

    cudaFuncSetAttribute(proj_mma_kernel,
                         cudaFuncAttributeMaxDynamicSharedMemorySize, OPER_SMEM);
    cudaFuncSetAttribute(stats_mma_kernel,
                         cudaFuncAttributeMaxDynamicSharedMemorySize, OPER_SMEM);
    cudaFuncSetAttribute(av_fused_kernel,
                         cudaFuncAttributeMaxDynamicSharedMemorySize, AVF_SMEM);
    cudaFuncSetAttribute(oproj_mma_kernel,
                         cudaFuncAttributeMaxDynamicSharedMemorySize, OPER_SMEM);

    dim3 projGrid(DM / 128, MQ / 128, 3);  // (4, 64, 3)
    proj_mma_kernel<<<projGrid, 256, OPER_SMEM>>>(queries, keys, values,
                                                  Wq, Wk, Wv, bq, bk, bv);

    dim3 statsGrid(SS / 128, SS / 128, BHN);  // (16, 16, 32)
    stats_mma_kernel<<<statsGrid, 256, OPER_SMEM>>>(mask);

    reduce_stats_kernel<<<(BHN * SS) / 8, 256>>>();

    dim3 avGrid(BHN, SS / 128);            // (32, 16)
    av_fused_kernel<<<avGrid, 256, AVF_SMEM>>>(mask, att);

    dim3 oGrid(DM / 128, MQ / 128);        // (4, 64)
    oproj_mma_kernel<<<oGrid, 256, OPER_SMEM>>>(Wo, bo, out);
}

// round 15
// speedup vs baseline: 1.1513x; 1.1513x over previous
#include <cuda_runtime.h>
#include <cuda_bf16.h>
#include <cstdint>
#include <cstddef>

// Problem constants
#define Hh      8
#define SS      2048
#define DM      512
#define DH      64
#define BATCH   4
#define BHN     (BATCH * Hh)          // 32
#define MQ      (BATCH * SS)          // 8192
#define OUT_ELEMS ((size_t)BATCH * SS * DM)  // 4194304
#define NXBLK   (SS / 128)            // 16 key-tile blocks per row

// Scratch (allocation-free: __device__ globals).
__device__ __nv_bfloat16 g_Qh [BHN * SS * DH];
__device__ __nv_bfloat16 g_Ql [BHN * SS * DH];
__device__ __nv_bfloat16 g_Kh [BHN * SS * DH];
__device__ __nv_bfloat16 g_Kl [BHN * SS * DH];
__device__ __nv_bfloat16 g_Vth[BHN * DH * SS];   // V^T hi: [bh][d][s]
__device__ __nv_bfloat16 g_Vtl[BHN * DH * SS];   // V^T lo
__device__ __nv_bfloat16 g_Hh [BHN * SS * DH];   // attn-out hi: [bh][s][d]
__device__ __nv_bfloat16 g_Hl [BHN * SS * DH];   // attn-out lo
__device__ float2 g_stats [(size_t)BHN * SS * NXBLK]; // per-(row, kblock) {M, S}
__device__ float2 g_rowMS [(size_t)BHN * SS];         // per-row {M, 1/S}

// ===========================================================================
// Warp-level MMA helpers (sm_80-compatible PTX)
// ===========================================================================
__device__ __forceinline__ uint32_t smem_u32(const void* p) {
    uint32_t a;
    asm("{ .reg .u64 t; cvta.to.shared.u64 t, %1; cvt.u32.u64 %0, t; }"
        : "=r"(a) : "l"(p));
    return a;
}
__device__ __forceinline__ void mma16816(float* c, const uint32_t* a, const uint32_t* b) {
    asm volatile(
        "mma.sync.aligned.m16n8k16.row.col.f32.bf16.bf16.f32 "
        "{%0,%1,%2,%3}, {%4,%5,%6,%7}, {%8,%9}, {%0,%1,%2,%3};"
        : "+f"(c[0]), "+f"(c[1]), "+f"(c[2]), "+f"(c[3])
        : "r"(a[0]), "r"(a[1]), "r"(a[2]), "r"(a[3]), "r"(b[0]), "r"(b[1]));
}
__device__ __forceinline__ void ldm_x4(uint32_t* r, uint32_t addr) {
    asm volatile("ldmatrix.sync.aligned.m8n8.x4.shared.b16 {%0,%1,%2,%3}, [%4];"
        : "=r"(r[0]), "=r"(r[1]), "=r"(r[2]), "=r"(r[3]) : "r"(addr));
}
__device__ __forceinline__ void ldm_x2(uint32_t* r, uint32_t addr) {
    asm volatile("ldmatrix.sync.aligned.m8n8.x2.shared.b16 {%0,%1}, [%2];"
        : "=r"(r[0]), "=r"(r[1]) : "r"(addr));
}
__device__ __forceinline__ void split_bf16(float v, __nv_bfloat16& h, __nv_bfloat16& l) {
    h = __float2bfloat16(v);
    l = __float2bfloat16(v - __bfloat162float(h));
}

#define SPAD  72    // operand row pitch in bf16 elems (144B), conflict-free ldmatrix
#define FPITCH 132  // fp32 epilogue staging pitch (floats)

// smem tile offsets (bf16 elems) for 4-operand kernels
#define T_AH 0
#define T_AL (128 * SPAD)
#define T_BH (2 * 128 * SPAD)
#define T_BL (3 * 128 * SPAD)
#define OPER_SMEM (4 * 128 * SPAD * 2)    // 73728 B

// av smem offsets
#define AV_AH 0
#define AV_AL (128 * SPAD)
#define AV_VH (2 * 128 * SPAD)
#define AV_VL (2 * 128 * SPAD + 64 * SPAD)
#define AV_SMEM ((2 * 128 * SPAD + 2 * 64 * SPAD) * 2)   // 55296 B

// ---------------------------------------------------------------------------
// Shared mainloop body (A/B hi/lo compensated, fragment-reuse version):
// per ks: load aH, bH -> aH*bH ; load bL -> aH*bL ; load aL -> aL*bH
// ---------------------------------------------------------------------------
#define COMP_MAINLOOP_4x4(sbase, arow, acol8, brow, bcol8, acc)              \
    _Pragma("unroll")                                                        \
    for (int ks = 0; ks < 4; ks++) {                                         \
        const int k0 = ks * 16;                                              \
        uint32_t aH[4][4], aL[4][4], bH[4][2], bL[4][2];                     \
        _Pragma("unroll")                                                    \
        for (int mt = 0; mt < 4; mt++)                                       \
            ldm_x4(aH[mt], (sbase) + 2u * (T_AH + ((arow) + mt*16) * SPAD + k0 + (acol8))); \
        _Pragma("unroll")                                                    \
        for (int nt = 0; nt < 4; nt++)                                       \
            ldm_x2(bH[nt], (sbase) + 2u * (T_BH + ((brow) + nt*8) * SPAD + k0 + (bcol8))); \
        _Pragma("unroll")                                                    \
        for (int mt = 0; mt < 4; mt++)                                       \
            _Pragma("unroll")                                                \
            for (int nt = 0; nt < 4; nt++)                                   \
                mma16816(acc[mt][nt], aH[mt], bH[nt]);                       \
        _Pragma("unroll")                                                    \
        for (int nt = 0; nt < 4; nt++)                                       \
            ldm_x2(bL[nt], (sbase) + 2u * (T_BL + ((brow) + nt*8) * SPAD + k0 + (bcol8))); \
        _Pragma("unroll")                                                    \
        for (int mt = 0; mt < 4; mt++)                                       \
            _Pragma("unroll")                                                \
            for (int nt = 0; nt < 4; nt++)                                   \
                mma16816(acc[mt][nt], aH[mt], bL[nt]);                       \
        _Pragma("unroll")                                                    \
        for (int mt = 0; mt < 4; mt++)                                       \
            ldm_x4(aL[mt], (sbase) + 2u * (T_AL + ((arow) + mt*16) * SPAD + k0 + (acol8))); \
        _Pragma("unroll")                                                    \
        for (int mt = 0; mt < 4; mt++)                                       \
            _Pragma("unroll")                                                \
            for (int nt = 0; nt < 4; nt++)                                   \
                mma16816(acc[mt][nt], aL[mt], bH[nt]);                       \
    }

// ---------------------------------------------------------------------------
// Kernel 1: merged QKV projection via mma.sync, compensated hi/lo.
// blockIdx.z: 0->Q, 1->K ([bh][s][d] hi/lo), 2->V^T ([bh][d][s])
// grid (4, 64, 3), block 256 (8 warps: 2 x 4, each m64 x n32)
// ---------------------------------------------------------------------------
__global__ __launch_bounds__(256, 2)
void proj_mma_kernel(const float* __restrict__ Xq, const float* __restrict__ Xk,
                     const float* __restrict__ Xv,
                     const float* __restrict__ Wq, const float* __restrict__ Wk,
                     const float* __restrict__ Wv,
                     const float* __restrict__ bq, const float* __restrict__ bk,
                     const float* __restrict__ bv)
{
    extern __shared__ __nv_bfloat16 sm[];
    const int which = blockIdx.z;
    const float* X    = (which == 0) ? Xq : (which == 1) ? Xk : Xv;
    const float* W    = (which == 0) ? Wq : (which == 1) ? Wk : Wv;
    const float* bias = (which == 0) ? bq : (which == 1) ? bk : bv;

    const int t    = threadIdx.x;
    const int wid  = t >> 5;
    const int lane = t & 31;
    const int m0   = blockIdx.y * 128;
    const int n0   = blockIdx.x * 128;

    const uint32_t sbase = smem_u32(sm);
    const int warp_m = wid >> 2;
    const int warp_n = wid & 3;

    float acc[4][4][4];
#pragma unroll
    for (int mt = 0; mt < 4; mt++)
#pragma unroll
        for (int nt = 0; nt < 4; nt++)
#pragma unroll
            for (int e = 0; e < 4; e++) acc[mt][nt][e] = 0.f;

    const int l16   = lane & 15;
    const int arow  = warp_m * 64 + (lane & 15);
    const int acol8 = (lane >> 4) * 8;
    const int brow  = warp_n * 32 + (l16 & 7);
    const int bcol8 = (l16 >> 3) * 8;

    const int lr_base = t >> 4;     // 0..15
    const int lcol    = (t & 15) * 4;

    for (int kb = 0; kb < DM; kb += 64) {
#pragma unroll
        for (int p = 0; p < 8; p++) {
            const int row = lr_base + p * 16;
            float4 xv = *(const float4*)(X + (size_t)(m0 + row) * DM + kb + lcol);
            float4 wv = *(const float4*)(W + (size_t)(n0 + row) * DM + kb + lcol);
            __nv_bfloat16 h0,h1,h2,h3,l0,l1,l2,l3;
            split_bf16(xv.x,h0,l0); split_bf16(xv.y,h1,l1);
            split_bf16(xv.z,h2,l2); split_bf16(xv.w,h3,l3);
            __nv_bfloat162* pa = (__nv_bfloat162*)(sm + T_AH + row * SPAD + lcol);
            pa[0] = __nv_bfloat162(h0,h1); pa[1] = __nv_bfloat162(h2,h3);
            __nv_bfloat162* qa = (__nv_bfloat162*)(sm + T_AL + row * SPAD + lcol);
            qa[0] = __nv_bfloat162(l0,l1); qa[1] = __nv_bfloat162(l2,l3);
            split_bf16(wv.x,h0,l0); split_bf16(wv.y,h1,l1);
            split_bf16(wv.z,h2,l2); split_bf16(wv.w,h3,l3);
            __nv_bfloat162* pb = (__nv_bfloat162*)(sm + T_BH + row * SPAD + lcol);
            pb[0] = __nv_bfloat162(h0,h1); pb[1] = __nv_bfloat162(h2,h3);
            __nv_bfloat162* qb = (__nv_bfloat162*)(sm + T_BL + row * SPAD + lcol);
            qb[0] = __nv_bfloat162(l0,l1); qb[1] = __nv_bfloat162(l2,l3);
        }
        __syncthreads();

        COMP_MAINLOOP_4x4(sbase, arow, acol8, brow, bcol8, acc)

        __syncthreads();
    }

    const int b_  = m0 >> 11;
    const int lr0 = warp_m * 64 + (lane >> 2);
    const int cb0 = warp_n * 32 + (lane & 3) * 2;
#pragma unroll
    for (int mt = 0; mt < 4; mt++) {
#pragma unroll
        for (int rr = 0; rr < 2; rr++) {
            const int s_ = (m0 & 2047) + lr0 + mt * 16 + rr * 8;
#pragma unroll
            for (int nt = 0; nt < 4; nt++) {
                const int n  = n0 + cb0 + nt * 8;
                const int h  = n >> 6, d = n & 63;
                const int bh = b_ * Hh + h;
                const float v0 = acc[mt][nt][rr*2+0] + bias[n];
                const float v1 = acc[mt][nt][rr*2+1] + bias[n+1];
                __nv_bfloat16 h0,h1,l0,l1;
                split_bf16(v0,h0,l0); split_bf16(v1,h1,l1);
                if (which == 2) {
                    const size_t i0 = ((size_t)bh * DH + d) * SS + s_;
                    const size_t i1 = ((size_t)bh * DH + d + 1) * SS + s_;
                    g_Vth[i0] = h0; g_Vtl[i0] = l0;
                    g_Vth[i1] = h1; g_Vtl[i1] = l1;
                } else {
                    const size_t idx = ((size_t)bh * SS + s_) * DH + d;
                    if (which == 0) {
                        *(__nv_bfloat162*)(g_Qh + idx) = __nv_bfloat162(h0,h1);
                        *(__nv_bfloat162*)(g_Ql + idx) = __nv_bfloat162(l0,l1);
                    } else {
                        *(__nv_bfloat162*)(g_Kh + idx) = __nv_bfloat162(h0,h1);
                        *(__nv_bfloat162*)(g_Kl + idx) = __nv_bfloat162(l0,l1);
                    }
                }
            }
        }
    }
}

// ---------------------------------------------------------------------------
// Kernel 2: scores via mma.sync + coalesced smem-staged epilogue + softmax stats.
// grid (16, 16, 32), block 256
// ---------------------------------------------------------------------------
__global__ __launch_bounds__(256, 2)
void scores_mma_kernel(const float* __restrict__ mask, float* __restrict__ att)
{
    extern __shared__ __nv_bfloat16 sm[];
    const int t    = threadIdx.x;
    const int wid  = t >> 5;
    const int lane = t & 31;

    const int bh = blockIdx.z;
    const int m0 = blockIdx.y * 128;
    const int n0 = blockIdx.x * 128;

    {
        const size_t rb = (size_t)bh * SS * DH;
        const int qi = t & 7;
#pragma unroll
        for (int p = 0; p < 4; p++) {
            const int row = (t >> 3) + p * 32;
            const size_t qoff = rb + (size_t)(m0 + row) * DH + qi * 8;
            const size_t koff = rb + (size_t)(n0 + row) * DH + qi * 8;
            *(uint4*)(sm + T_AH + row * SPAD + qi * 8) = *(const uint4*)(g_Qh + qoff);
            *(uint4*)(sm + T_AL + row * SPAD + qi * 8) = *(const uint4*)(g_Ql + qoff);
            *(uint4*)(sm + T_BH + row * SPAD + qi * 8) = *(const uint4*)(g_Kh + koff);
            *(uint4*)(sm + T_BL + row * SPAD + qi * 8) = *(const uint4*)(g_Kl + koff);
        }
    }
    __syncthreads();

    const uint32_t sbase = smem_u32(sm);
    const int warp_m = wid >> 2;
    const int warp_n = wid & 3;

    float acc[4][4][4];
#pragma unroll
    for (int mt = 0; mt < 4; mt++)
#pragma unroll
        for (int nt = 0; nt < 4; nt++)
#pragma unroll
            for (int e = 0; e < 4; e++) acc[mt][nt][e] = 0.f;

    const int l16   = lane & 15;
    const int arow  = warp_m * 64 + (lane & 15);
    const int acol8 = (lane >> 4) * 8;
    const int brow  = warp_n * 32 + (l16 & 7);
    const int bcol8 = (l16 >> 3) * 8;

    COMP_MAINLOOP_4x4(sbase, arow, acol8, brow, bcol8, acc)

    __syncthreads();
    float* smf = (float*)sm;
    {
        const int lr0 = warp_m * 64 + (lane >> 2);
        const int cb0 = warp_n * 32 + (lane & 3) * 2;
#pragma unroll
        for (int mt = 0; mt < 4; mt++) {
            const int r0 = lr0 + mt * 16;
#pragma unroll
            for (int nt = 0; nt < 4; nt++) {
                const int cb = cb0 + nt * 8;
                *(float2*)(smf + (size_t)r0 * FPITCH + cb) =
                    make_float2(acc[mt][nt][0] * 0.125f, acc[mt][nt][1] * 0.125f);
                *(float2*)(smf + (size_t)(r0 + 8) * FPITCH + cb) =
                    make_float2(acc[mt][nt][2] * 0.125f, acc[mt][nt][3] * 0.125f);
            }
        }
    }
    __syncthreads();

    {
        const int lrb = t >> 4;          // 0..15
        const int c0  = (t & 15) * 4;    // 0..60
#pragma unroll
        for (int p = 0; p < 8; p++) {
            const int row  = lrb + p * 16;
            const int grow = m0 + row;
            float4 v0 = *(float4*)(smf + (size_t)row * FPITCH + c0);
            float4 v1 = *(float4*)(smf + (size_t)row * FPITCH + c0 + 64);
            float4 k0 = *(const float4*)(mask + (size_t)grow * SS + n0 + c0);
            float4 k1 = *(const float4*)(mask + (size_t)grow * SS + n0 + c0 + 64);
            v0.x += k0.x; v0.y += k0.y; v0.z += k0.z; v0.w += k0.w;
            v1.x += k1.x; v1.y += k1.y; v1.z += k1.z; v1.w += k1.w;
            float* arow_p = att + ((size_t)bh * SS + grow) * SS + n0;
            *(float4*)(arow_p + c0)      = v0;
            *(float4*)(arow_p + c0 + 64) = v1;
            float mx = fmaxf(fmaxf(fmaxf(v0.x, v0.y), fmaxf(v0.z, v0.w)),
                             fmaxf(fmaxf(v1.x, v1.y), fmaxf(v1.z, v1.w)));
#pragma unroll
            for (int off = 1; off < 16; off <<= 1)
                mx = fmaxf(mx, __shfl_xor_sync(0xFFFFFFFFu, mx, off));
            float s = __expf(v0.x - mx) + __expf(v0.y - mx) + __expf(v0.z - mx) + __expf(v0.w - mx)
                    + __expf(v1.x - mx) + __expf(v1.y - mx) + __expf(v1.z - mx) + __expf(v1.w - mx);
#pragma unroll
            for (int off = 1; off < 16; off <<= 1)
                s += __shfl_xor_sync(0xFFFFFFFFu, s, off);
            if ((t & 15) == 0)
                g_stats[((size_t)bh * SS + grow) * NXBLK + blockIdx.x] = make_float2(mx, s);
        }
    }
}

// ---------------------------------------------------------------------------
// Kernel 3: reduce per-row partials -> {M, 1/S}
// ---------------------------------------------------------------------------
__global__ __launch_bounds__(256)
void reduce_stats_kernel()
{
    const size_t r = (size_t)blockIdx.x * 256 + threadIdx.x;
    const float2* p = g_stats + r * NXBLK;
    float2 loc[NXBLK];
#pragma unroll
    for (int i = 0; i < NXBLK; i++) loc[i] = p[i];
    float M = loc[0].x;
#pragma unroll
    for (int i = 1; i < NXBLK; i++) M = fmaxf(M, loc[i].x);
    float S = 0.f;
#pragma unroll
    for (int i = 0; i < NXBLK; i++) S += loc[i].y * __expf(loc[i].x - M);
    g_rowMS[r] = make_float2(M, 1.0f / S);
}

// ---------------------------------------------------------------------------
// Kernel 4: av (512-thread variant). Same 128-row tile & memory pattern as R12,
// but 16 warps (m32 x n16 per warp) for 2x warps/SM at 2 CTAs.
// grid (16, 32): x = m-tile(128), y = bh. block 512.
// ---------------------------------------------------------------------------
__global__ __launch_bounds__(512, 2)
void av_mma_kernel(float* __restrict__ att)
{
    extern __shared__ __nv_bfloat16 sm[];
    const int t    = threadIdx.x;
    const int wid  = t >> 5;          // 0..15
    const int lane = t & 31;

    const int bh = blockIdx.y;
    const int m0 = blockIdx.x * 128;

    const uint32_t sbase = smem_u32(sm);
    const int warp_m = wid >> 2;      // 0..3 -> 32-row band
    const int warp_n = wid & 3;       // 0..3 -> 16 d-cols

    float acc[2][2][4];
#pragma unroll
    for (int mt = 0; mt < 2; mt++)
#pragma unroll
        for (int nt = 0; nt < 2; nt++)
#pragma unroll
            for (int e = 0; e < 4; e++) acc[mt][nt][e] = 0.f;

    const int l16   = lane & 15;
    const int arow  = warp_m * 32 + l16;
    const int acol8 = (lane >> 4) * 8;
    const int brow  = warp_n * 16 + (l16 & 7);
    const int bcol8 = (l16 >> 3) * 8;

    const int lrb = t >> 4;           // att: 16 thr/row -> rows 0..31, 4 passes
    const int c0  = (t & 15) * 4;
    const int vrow = t >> 3;          // V: 8 thr/row -> rows 0..63, 1 pass
    const int vqi  = t & 7;

    float2 ms[4];
#pragma unroll
    for (int p = 0; p < 4; p++)
        ms[p] = g_rowMS[(size_t)bh * SS + m0 + lrb + p * 32];

    for (int kb = 0; kb < SS; kb += 64) {
        // att chunk: normalize + write back + hi/lo split into smem
#pragma unroll
        for (int p = 0; p < 4; p++) {
            const int row = lrb + p * 32;
            float* ap = att + ((size_t)bh * SS + m0 + row) * SS + kb + c0;
            float4 v = *(const float4*)ap;
            const float M = ms[p].x, inv = ms[p].y;
            v.x = __expf(v.x - M) * inv;
            v.y = __expf(v.y - M) * inv;
            v.z = __expf(v.z - M) * inv;
            v.w = __expf(v.w - M) * inv;
            *(float4*)ap = v;
            __nv_bfloat16 h0,h1,h2,h3,l0,l1,l2,l3;
            split_bf16(v.x,h0,l0); split_bf16(v.y,h1,l1);
            split_bf16(v.z,h2,l2); split_bf16(v.w,h3,l3);
            __nv_bfloat162* ph = (__nv_bfloat162*)(sm + AV_AH + row * SPAD + c0);
            ph[0] = __nv_bfloat162(h0,h1); ph[1] = __nv_bfloat162(h2,h3);
            __nv_bfloat162* pl = (__nv_bfloat162*)(sm + AV_AL + row * SPAD + c0);
            pl[0] = __nv_bfloat162(l0,l1); pl[1] = __nv_bfloat162(l2,l3);
        }
        // V^T chunk: 64 d-rows x 64 s-cols bf16, 8 thr/row, single pass
        {
            const size_t voff = ((size_t)bh * DH + vrow) * SS + kb + vqi * 8;
            *(uint4*)(sm + AV_VH + vrow * SPAD + vqi * 8) = *(const uint4*)(g_Vth + voff);
            *(uint4*)(sm + AV_VL + vrow * SPAD + vqi * 8) = *(const uint4*)(g_Vtl + voff);
        }
        __syncthreads();

#pragma unroll
        for (int ks = 0; ks < 4; ks++) {
            const int k0 = ks * 16;
            uint32_t aH[2][4], aL[2][4], bH[2][2], bL[2][2];
#pragma unroll
            for (int mt = 0; mt < 2; mt++) {
                ldm_x4(aH[mt], sbase + 2u * (AV_AH + (arow + mt*16) * SPAD + k0 + acol8));
                ldm_x4(aL[mt], sbase + 2u * (AV_AL + (arow + mt*16) * SPAD + k0 + acol8));
            }
#pragma unroll
            for (int nt = 0; nt < 2; nt++) {
                ldm_x2(bH[nt], sbase + 2u * (AV_VH + (brow + nt*8) * SPAD + k0 + bcol8));
                ldm_x2(bL[nt], sbase + 2u * (AV_VL + (brow + nt*8) * SPAD + k0 + bcol8));
            }
#pragma unroll
            for (int mt = 0; mt < 2; mt++)
#pragma unroll
                for (int nt = 0; nt < 2; nt++) {
                    mma16816(acc[mt][nt], aH[mt], bH[nt]);
                    mma16816(acc[mt][nt], aH[mt], bL[nt]);
                    mma16816(acc[mt][nt], aL[mt], bH[nt]);
                }
        }
        __syncthreads();
    }

    // Epilogue -> g_Hh/g_Hl bf16 hi/lo, [bh][s][d]
    const int orow = m0 + warp_m * 32 + (lane >> 2);
    const int ocb0 = warp_n * 16 + (lane & 3) * 2;
#pragma unroll
    for (int mt = 0; mt < 2; mt++) {
#pragma unroll
        for (int rr = 0; rr < 2; rr++) {
            const int r = orow + mt * 16 + rr * 8;
#pragma unroll
            for (int nt = 0; nt < 2; nt++) {
                const int cb = ocb0 + nt * 8;
                const float v0 = acc[mt][nt][rr*2+0];
                const float v1 = acc[mt][nt][rr*2+1];
                __nv_bfloat16 h0,h1,l0,l1;
                split_bf16(v0,h0,l0); split_bf16(v1,h1,l1);
                const size_t idx = ((size_t)bh * SS + r) * DH + cb;
                *(__nv_bfloat162*)(g_Hh + idx) = __nv_bfloat162(h0,h1);
                *(__nv_bfloat162*)(g_Hl + idx) = __nv_bfloat162(l0,l1);
            }
        }
    }
}

// ---------------------------------------------------------------------------
// Kernel 5: output projection via mma.sync: out = H @ Wo^T + bo.
// grid (4, 64), block 256
// ---------------------------------------------------------------------------
__global__ __launch_bounds__(256, 2)
void oproj_mma_kernel(const float* __restrict__ Wo, const float* __restrict__ bo,
                      float* __restrict__ out)
{
    extern __shared__ __nv_bfloat16 sm[];
    const int t    = threadIdx.x;
    const int wid  = t >> 5;
    const int lane = t & 31;
    const int m0   = blockIdx.y * 128;
    const int n0   = blockIdx.x * 128;
    const int b_   = m0 >> 11;
    const int s0   = m0 & 2047;

    const uint32_t sbase = smem_u32(sm);
    const int warp_m = wid >> 2;
    const int warp_n = wid & 3;

    float acc[4][4][4];
#pragma unroll
    for (int mt = 0; mt < 4; mt++)
#pragma unroll
        for (int nt = 0; nt < 4; nt++)
#pragma unroll
            for (int e = 0; e < 4; e++) acc[mt][nt][e] = 0.f;

    const int l16   = lane & 15;
    const int arow  = warp_m * 64 + (lane & 15);
    const int acol8 = (lane >> 4) * 8;
    const int brow  = warp_n * 32 + (l16 & 7);
    const int bcol8 = (l16 >> 3) * 8;

    const int aqi = t & 7;
    const int wlr = t >> 4;
    const int wc0 = (t & 15) * 4;

    for (int kb = 0; kb < 8; kb++) {
#pragma unroll
        for (int p = 0; p < 4; p++) {
            const int row = (t >> 3) + p * 32;
            const size_t hoff = (((size_t)(b_ * Hh + kb) * SS) + s0 + row) * DH + aqi * 8;
            *(uint4*)(sm + T_AH + row * SPAD + aqi * 8) = *(const uint4*)(g_Hh + hoff);
            *(uint4*)(sm + T_AL + row * SPAD + aqi * 8) = *(const uint4*)(g_Hl + hoff);
        }
#pragma unroll
        for (int p = 0; p < 8; p++) {
            const int row = wlr + p * 16;
            float4 wv = *(const float4*)(Wo + (size_t)(n0 + row) * DM + kb * 64 + wc0);
            __nv_bfloat16 h0,h1,h2,h3,l0,l1,l2,l3;
            split_bf16(wv.x,h0,l0); split_bf16(wv.y,h1,l1);
            split_bf16(wv.z,h2,l2); split_bf16(wv.w,h3,l3);
            __nv_bfloat162* pb = (__nv_bfloat162*)(sm + T_BH + row * SPAD + wc0);
            pb[0] = __nv_bfloat162(h0,h1); pb[1] = __nv_bfloat162(h2,h3);
            __nv_bfloat162* qb = (__nv_bfloat162*)(sm + T_BL + row * SPAD + wc0);
            qb[0] = __nv_bfloat162(l0,l1); qb[1] = __nv_bfloat162(l2,l3);
        }
        __syncthreads();

        COMP_MAINLOOP_4x4(sbase, arow, acol8, brow, bcol8, acc)

        __syncthreads();
    }

    const int lr0 = warp_m * 64 + (lane >> 2);
    const int cb0 = warp_n * 32 + (lane & 3) * 2;
#pragma unroll
    for (int mt = 0; mt < 4; mt++) {
#pragma unroll
        for (int rr = 0; rr < 2; rr++) {
            const int mm = m0 + lr0 + mt * 16 + rr * 8;
#pragma unroll
            for (int nt = 0; nt < 4; nt++) {
                const int n = n0 + cb0 + nt * 8;
                *(float2*)(out + (size_t)mm * DM + n) =
                    make_float2(acc[mt][nt][rr*2+0] + bo[n],
                                acc[mt][nt][rr*2+1] + bo[n+1]);
            }
        }
    }
}

// ---------------------------------------------------------------------------
extern "C" void kernel_launch(void* const* d_in, const int* in_sizes, int n_in,
                              void* d_out, int out_size)
{
    const float* queries = (const float*)d_in[0];
    const float* keys    = (const float*)d_in[1];
    const float* values  = (const float*)d_in[2];
    const float* mask    = (const float*)d_in[3];
    const float* Wq      = (const float*)d_in[4];
    const float* bq      = (const float*)d_in[5];
    const float* Wk      = (const float*)d_in[6];
    const float* bk      = (const float*)d_in[7];
    const float* Wv      = (const float*)d_in[8];
    const float* bv      = (const float*)d_in[9];
    const float* Wo      = (const float*)d_in[10];
    const float* bo      = (const float*)d_in[11];

    float* out = (float*)d_out;            // [4, 2048, 512]
    float* att = out + OUT_ELEMS;          // [4, 8, 2048, 2048]

    cudaFuncSetAttribute(proj_mma_kernel,
                         cudaFuncAttributeMaxDynamicSharedMemorySize, OPER_SMEM);
    cudaFuncSetAttribute(scores_mma_kernel,
                         cudaFuncAttributeMaxDynamicSharedMemorySize, OPER_SMEM);
    cudaFuncSetAttribute(av_mma_kernel,
                         cudaFuncAttributeMaxDynamicSharedMemorySize, AV_SMEM);
    cudaFuncSetAttribute(oproj_mma_kernel,
                         cudaFuncAttributeMaxDynamicSharedMemorySize, OPER_SMEM);

    dim3 projGrid(DM / 128, MQ / 128, 3);  // (4, 64, 3)
    proj_mma_kernel<<<projGrid, 256, OPER_SMEM>>>(queries, keys, values,
                                                  Wq, Wk, Wv, bq, bk, bv);

    dim3 scoreGrid(SS / 128, SS / 128, BHN);  // (16, 16, 32)
    scores_mma_kernel<<<scoreGrid, 256, OPER_SMEM>>>(mask, att);

    reduce_stats_kernel<<<(BHN * SS) / 256, 256>>>();

    dim3 avGrid(SS / 128, BHN);            // (16, 32)
    av_mma_kernel<<<avGrid, 512, AV_SMEM>>>(att);

    dim3 oGrid(DM / 128, MQ / 128);        // (4, 64)
    oproj_mma_kernel<<<oGrid, 256, OPER_SMEM>>>(Wo, bo, out);
}